// round 1
// baseline (speedup 1.0000x reference)
#include <cuda_runtime.h>
#include <math.h>

// Problem constants (fixed shapes per reference):
//   x:  (2, 32768, 3) f32
//   deformed_verts / mean_shape_verts: (2, 8192, 3) f32, subsampled ::8 -> M=1024
//   out: (2, 32768, 3) f32
//   SIGMA=0.5 -> inv_sigma2 = 4
#define B_    2
#define N_    32768
#define D_    3
#define MFULL 8192
#define M_    1024
#define SUB_  8
#define EVAL_THREADS 256

// Scan tables (built per launch from inputs; __device__ globals = legal scratch).
__device__ float  g_sdv[B_][D_][M_];        // sorted dv
__device__ double g_pA [B_][D_][M_ + 1];    // prefix  Sum_{i<k}  exp(+4 dv_i)
__device__ double g_pMA[B_][D_][M_ + 1];    // prefix  Sum_{i<k}  mv_i*exp(+4 dv_i)
__device__ double g_sB [B_][D_][M_ + 1];    // suffix  Sum_{i>=k} exp(-4 dv_i)
__device__ double g_sMB[B_][D_][M_ + 1];    // suffix  Sum_{i>=k} mv_i*exp(-4 dv_i)

// ---------------------------------------------------------------------------
// Kernel 1: per (b,d) — sort 1024 (dv, mv) pairs, build fp64 scan tables.
// grid = B_*D_ = 6 blocks, block = 1024 threads.
// ---------------------------------------------------------------------------
__global__ void __launch_bounds__(M_, 1)
build_tables(const float* __restrict__ dv_in, const float* __restrict__ mv_in) {
    const int b = blockIdx.x / D_;
    const int d = blockIdx.x % D_;
    const int t = threadIdx.x;

    __shared__ float  s_key[M_];
    __shared__ float  s_val[M_];
    __shared__ double s_v[4][M_];
    __shared__ double s_ch[4][32];

    const int src = (b * MFULL + t * SUB_) * D_ + d;
    s_key[t] = dv_in[src];
    s_val[t] = mv_in[src];
    __syncthreads();

    // Bitonic sort ascending by key (canonical one-element-per-thread form).
    for (int k = 2; k <= M_; k <<= 1) {
        for (int j = k >> 1; j > 0; j >>= 1) {
            const int ixj = t ^ j;
            if (ixj > t) {
                const bool up = ((t & k) == 0);
                const float kt = s_key[t], kx = s_key[ixj];
                const bool sw = up ? (kt > kx) : (kt < kx);
                if (sw) {
                    s_key[t] = kx; s_key[ixj] = kt;
                    const float vt = s_val[t];
                    s_val[t] = s_val[ixj]; s_val[ixj] = vt;
                }
            }
            __syncthreads();
        }
    }

    g_sdv[b][d][t] = s_key[t];

    const double dvd = (double)s_key[t];
    const double mvd = (double)s_val[t];
    const double ap  = exp( 4.0 * dvd);
    const double am  = exp(-4.0 * dvd);
    s_v[0][t] = ap;
    s_v[1][t] = mvd * ap;
    s_v[2][t] = am;
    s_v[3][t] = mvd * am;
    __syncthreads();

    // Warps 0..3 each scan one table. Tables 0,1: forward EXCLUSIVE prefix
    // (out[k] = sum_{i<k}). Tables 2,3: backward INCLUSIVE suffix
    // (out[k] = sum_{i>=k}, out[M]=0). Chunked: 32 lanes x 32-element chunks.
    const int w = t >> 5, l = t & 31;
    if (w < 4) {
        const double* v = s_v[w];
        double* outp = (w == 0) ? g_pA[b][d]
                     : (w == 1) ? g_pMA[b][d]
                     : (w == 2) ? g_sB[b][d]
                                : g_sMB[b][d];
        // 1) chunk totals
        double cs = 0.0;
        for (int i = 0; i < 32; i++) cs += v[l * 32 + i];
        s_ch[w][l] = cs;
        __syncwarp();
        // 2) scan of chunk totals by lane 0
        if (l == 0) {
            if (w < 2) {
                double run = 0.0;
                for (int i = 0; i < 32; i++) { const double c = s_ch[w][i]; s_ch[w][i] = run; run += c; }
            } else {
                double run = 0.0;  // s_ch[i] := sum of chunks strictly after i
                for (int i = 31; i >= 0; i--) { const double c = s_ch[w][i]; s_ch[w][i] = run; run += c; }
            }
        }
        __syncwarp();
        // 3) rewalk chunk with carry-in
        double run = s_ch[w][l];
        if (w < 2) {
            for (int i = 0; i < 32; i++) {
                const int idx = l * 32 + i;
                outp[idx] = run;           // exclusive
                run += v[idx];
            }
            if (l == 31) outp[M_] = run;   // total
        } else {
            for (int i = 31; i >= 0; i--) {
                const int idx = l * 32 + i;
                run += v[idx];
                outp[idx] = run;           // inclusive suffix
            }
            if (l == 0) outp[M_] = 0.0;
        }
    }
}

// ---------------------------------------------------------------------------
// Kernel 2: one thread per output element (b,n,d).
//   k = #(sorted dv < x)  via branchless power-of-2 lower bound in SMEM,
//   out = (e^-4x * pMA[k] + e^+4x * sMB[k]) / (e^-4x * pA[k] + e^+4x * sB[k])
// grid = B_*N_*D_/256 = 768 blocks of 256.
// ---------------------------------------------------------------------------
__global__ void __launch_bounds__(EVAL_THREADS, 8)
eval_kernel(const float* __restrict__ x, float* __restrict__ out) {
    __shared__ float s_dv[D_][M_];

    const int tid = threadIdx.x;
    const int gid = blockIdx.x * EVAL_THREADS + tid;
    const int per_b_blocks = (N_ * D_) / EVAL_THREADS;   // 384
    const int b = blockIdx.x / per_b_blocks;

    // Stage sorted dv (this b, all 3 dims) into SMEM: 12 KB.
    const float* src = &g_sdv[b][0][0];
    float* dst = &s_dv[0][0];
    for (int i = tid; i < D_ * M_; i += EVAL_THREADS) dst[i] = src[i];
    __syncthreads();

    const int rem = gid - b * (N_ * D_);
    const int d   = rem % D_;
    const float xv = x[gid];

    // Branchless lower bound: k = count of arr[i] < xv, arr sorted ascending.
    const float* arr = s_dv[d];
    int k;
    if (arr[M_ - 1] < xv) {
        k = M_;
    } else {
        k = 0;
        #pragma unroll
        for (int s = M_ / 2; s >= 1; s >>= 1)
            if (arr[k + s - 1] < xv) k += s;
    }

    const float emf = expf(-4.0f * xv);
    const float epf = expf( 4.0f * xv);

    const double num = (double)emf * g_pMA[b][d][k] + (double)epf * g_sMB[b][d][k];
    const double den = (double)emf * g_pA [b][d][k] + (double)epf * g_sB [b][d][k];

    out[gid] = (float)num / (float)den;
}

// ---------------------------------------------------------------------------
extern "C" void kernel_launch(void* const* d_in, const int* in_sizes, int n_in,
                              void* d_out, int out_size) {
    const float* x  = (const float*)d_in[0];   // (B, N, D)
    const float* dv = (const float*)d_in[1];   // (B, MFULL, D)
    const float* mv = (const float*)d_in[2];   // (B, MFULL, D)
    // d_in[3] = deformation_parameters, unused by the reference math.
    float* out = (float*)d_out;

    build_tables<<<B_ * D_, M_>>>(dv, mv);
    eval_kernel<<<(B_ * N_ * D_) / EVAL_THREADS, EVAL_THREADS>>>(x, out);
}

// round 2
// speedup vs baseline: 1.4825x; 1.4825x over previous
#include <cuda_runtime.h>
#include <math.h>

// Shapes fixed by the reference:
//   x: (2, 32768, 3) f32; verts: (2, 8192, 3) f32 subsampled ::8 -> M=1024
//   out: (2, 32768, 3) f32;  inv_sigma2 = 4
#define B_    2
#define N_    32768
#define D_    3
#define MFULL 8192
#define M_    1024
#define SUB_  8
#define LUT_  2048
#define LUTP_ 2052          // padded (even) entries per (b,d)
#define EVAL_THREADS 256

// Separable identity: exp(-4|x-dv|) = e^{-4x}e^{+4dv} [dv<x] + e^{+4x}e^{-4dv} [dv>=x]
// -> sort dv, build prefix/suffix tables, per-x split point via LUT+tiny search.
__device__ float  g_sdv[B_][D_][M_];                 // sorted dv
__device__ __align__(128) unsigned short g_lut[B_][D_][LUTP_];
__device__ float2 g_rng[B_][D_];                     // {lo, LUT/(hi-lo)}
// g_tab[b][d][k][0] = {pA, pMA} (exclusive prefix of e^{4dv}, mv*e^{4dv})
// g_tab[b][d][k][1] = {sB, sMB} (inclusive suffix of e^{-4dv}, mv*e^{-4dv})
__device__ double2 g_tab[B_][D_][M_ + 1][2];

__device__ __forceinline__ void xstage(float& key, float& val, int t, int k, int j) {
    const float pk = __shfl_xor_sync(0xffffffffu, key, j);
    const float pv = __shfl_xor_sync(0xffffffffu, val, j);
    const bool up    = ((t & k) == 0);
    const bool lower = ((t & j) == 0);
    const bool take  = (lower == up) ? (pk < key) : (pk > key);
    if (take) { key = pk; val = pv; }
}

// ---------------------------------------------------------------------------
// Kernel 1: per (b,d) sort + fp64 scan tables + bucket LUT.  grid=6, block=1024
// ---------------------------------------------------------------------------
__global__ void __launch_bounds__(M_, 1)
build_tables(const float* __restrict__ dv_in, const float* __restrict__ mv_in) {
    const int b = blockIdx.x / D_;
    const int d = blockIdx.x % D_;
    const int t = threadIdx.x, lane = t & 31, w = t >> 5;

    __shared__ float  sk[2][M_];
    __shared__ float  sv[2][M_];
    __shared__ float  s_sorted[M_];
    __shared__ double s_chp[2][32];
    __shared__ double s_chs[2][32];

    const int src = (b * MFULL + t * SUB_) * D_ + d;
    float key = dv_in[src];
    float val = mv_in[src];

    // Bitonic sort: phases k=2..32 entirely in registers via warp shuffles.
    #pragma unroll
    for (int k = 2; k <= 32; k <<= 1)
        #pragma unroll
        for (int j = k >> 1; j >= 1; j >>= 1)
            xstage(key, val, t, k, j);

    // Phases k=64..1024: j>=32 via double-buffered smem (1 bar/stage), j<=16 via shfl.
    int p = 0;
    for (int k = 64; k <= M_; k <<= 1) {
        for (int j = k >> 1; j >= 32; j >>= 1) {
            sk[p][t] = key; sv[p][t] = val;
            __syncthreads();
            const float pk = sk[p][t ^ j];
            const float pv = sv[p][t ^ j];
            const bool up = ((t & k) == 0), lower = ((t & j) == 0);
            const bool take = (lower == up) ? (pk < key) : (pk > key);
            if (take) { key = pk; val = pv; }
            p ^= 1;
        }
        #pragma unroll
        for (int j = 16; j >= 1; j >>= 1) xstage(key, val, t, k, j);
    }

    s_sorted[t] = key;
    g_sdv[b][d][t] = key;

    // Table terms: expf (1e-7 rel err) + fp64 accumulation.
    const float apf = expf( 4.0f * key);
    const float amf = expf(-4.0f * key);
    const double vd = (double)val;
    const double v0 = (double)apf;
    const double v1 = vd * (double)apf;
    const double v2 = (double)amf;
    const double v3 = vd * (double)amf;

    // Warp Kogge-Stone: inclusive prefix (v0,v1) and inclusive suffix (v2,v3).
    double i0 = v0, i1 = v1, i2 = v2, i3 = v3;
    #pragma unroll
    for (int s = 1; s < 32; s <<= 1) {
        double a = __shfl_up_sync(0xffffffffu, i0, s);   if (lane >= s)       i0 += a;
        double bq = __shfl_up_sync(0xffffffffu, i1, s);  if (lane >= s)       i1 += bq;
        double c = __shfl_down_sync(0xffffffffu, i2, s); if (lane < 32 - s)   i2 += c;
        double e = __shfl_down_sync(0xffffffffu, i3, s); if (lane < 32 - s)   i3 += e;
    }
    if (lane == 31) { s_chp[0][w] = i0; s_chp[1][w] = i1; }
    if (lane == 0)  { s_chs[0][w] = i2; s_chs[1][w] = i3; }
    __syncthreads();

    // Chunk-level scans: warps 0,1 -> exclusive prefix carries; 2,3 -> suffix carries.
    if (w < 2) {
        double ic = s_chp[w][lane];
        #pragma unroll
        for (int s = 1; s < 32; s <<= 1) { double a = __shfl_up_sync(0xffffffffu, ic, s); if (lane >= s) ic += a; }
        double ex = __shfl_up_sync(0xffffffffu, ic, 1);
        if (lane == 0) ex = 0.0;
        s_chp[w][lane] = ex;
    } else if (w < 4) {
        const int q = w - 2;
        double ic = s_chs[q][lane];
        #pragma unroll
        for (int s = 1; s < 32; s <<= 1) { double a = __shfl_down_sync(0xffffffffu, ic, s); if (lane < 32 - s) ic += a; }
        double ca = __shfl_down_sync(0xffffffffu, ic, 1);
        if (lane == 31) ca = 0.0;
        s_chs[q][lane] = ca;
    }
    __syncthreads();

    // Element-level exclusive prefix / inclusive suffix with chunk carries.
    double e0 = __shfl_up_sync(0xffffffffu, i0, 1); if (lane == 0) e0 = 0.0;
    double e1 = __shfl_up_sync(0xffffffffu, i1, 1); if (lane == 0) e1 = 0.0;
    e0 += s_chp[0][w];
    e1 += s_chp[1][w];
    const double sf2 = i2 + s_chs[0][w];
    const double sf3 = i3 + s_chs[1][w];

    g_tab[b][d][t][0] = make_double2(e0, e1);
    g_tab[b][d][t][1] = make_double2(sf2, sf3);
    if (t == M_ - 1) g_tab[b][d][M_][0] = make_double2(e0 + v0, e1 + v1);
    if (t == 0)      g_tab[b][d][M_][1] = make_double2(0.0, 0.0);

    // Bucket LUT: lut[q] = count(dv < lo + q*(hi-lo)/LUT).
    const float lo = s_sorted[0];
    const float hi = s_sorted[M_ - 1];
    const float span = hi - lo;
    const float inv  = span / (float)LUT_;
    if (t == 0) g_rng[b][d] = make_float2(lo, (float)LUT_ / span);

    #pragma unroll
    for (int rpt = 0; rpt < 2; rpt++) {
        const int q = t + rpt * M_;
        const float edge = lo + (float)q * inv;
        int kk = 0;
        #pragma unroll
        for (int s = M_ / 2; s >= 1; s >>= 1)
            if (s_sorted[kk + s - 1] < edge) kk += s;
        if (s_sorted[kk] < edge) kk++;            // kk <= 1023 here; may bump to 1024
        g_lut[b][d][q] = (unsigned short)kk;
    }
    if (t == 0) g_lut[b][d][LUT_] = (unsigned short)M_;  // x > hi safety
}

// ---------------------------------------------------------------------------
// Kernel 2: one thread per (b,n,d).  LUT -> tiny lower_bound -> closed form.
// ---------------------------------------------------------------------------
__global__ void __launch_bounds__(EVAL_THREADS, 8)
eval_kernel(const float* __restrict__ x, float* __restrict__ out) {
    __shared__ float s_dv[D_][M_];
    __shared__ __align__(4) unsigned short s_lut[D_][LUTP_];

    const int tid = threadIdx.x;
    const int gid = blockIdx.x * EVAL_THREADS + tid;
    const int per_b = (N_ * D_) / EVAL_THREADS;       // 384
    const int b = blockIdx.x / per_b;

    {
        const float* src = &g_sdv[b][0][0];
        float* dst = &s_dv[0][0];
        #pragma unroll
        for (int i = tid; i < D_ * M_; i += EVAL_THREADS) dst[i] = src[i];
        const unsigned int* lsrc = (const unsigned int*)&g_lut[b][0][0];
        unsigned int* ldst = (unsigned int*)&s_lut[0][0];
        for (int i = tid; i < D_ * LUTP_ / 2; i += EVAL_THREADS) ldst[i] = lsrc[i];
    }
    __syncthreads();

    const int rem = gid - b * (N_ * D_);
    const int d = rem % D_;
    const float xv = x[gid];
    const float2 rg = g_rng[b][d];

    int q = (int)((xv - rg.x) * rg.y);
    q = q < 0 ? 0 : (q > LUT_ - 1 ? LUT_ - 1 : q);

    int lo_ = s_lut[d][q];
    int hi_ = s_lut[d][q + 1];
    const float* arr = s_dv[d];
    while (lo_ < hi_) {
        const int mid = (lo_ + hi_) >> 1;
        if (arr[mid] < xv) lo_ = mid + 1; else hi_ = mid;
    }
    const int k = lo_;

    const double emf = (double)expf(-4.0f * xv);
    const double epf = (double)expf( 4.0f * xv);

    const double2 tp = g_tab[b][d][k][0];
    const double2 ts = g_tab[b][d][k][1];
    const double num = emf * tp.y + epf * ts.y;
    const double den = emf * tp.x + epf * ts.x;

    out[gid] = (float)num / (float)den;
}

// ---------------------------------------------------------------------------
extern "C" void kernel_launch(void* const* d_in, const int* in_sizes, int n_in,
                              void* d_out, int out_size) {
    const float* x  = (const float*)d_in[0];
    const float* dv = (const float*)d_in[1];
    const float* mv = (const float*)d_in[2];
    float* out = (float*)d_out;

    build_tables<<<B_ * D_, M_>>>(dv, mv);
    eval_kernel<<<(B_ * N_ * D_) / EVAL_THREADS, EVAL_THREADS>>>(x, out);
}